// round 17
// baseline (speedup 1.0000x reference)
#include <cuda_runtime.h>
#include <cstdint>
#include <math.h>

// Problem constants (fixed by reference setup_inputs)
#define NB 16
#define NH 1024
#define NW 1024
#define GRID_ELEMS (NB * NH * NW)   // 16777216 floats for odo_grid
#define K_OUT 64                    // 4 * B rows in odo

// Single-warp point kernel (proven in R10): no barriers, no smem, no sort.
// Lane b (<16) owns batch b: fp32 inverse affine map locates the candidate
// center (any true match is provably within integer offset +/-1: a lattice
// point mapping into the target unit square lies within 0.708px of the
// continuous preimage center). Serial 3x3 scan in (h outer, w inner) order
// collects keys already in increasing row-major order — argwhere order for
// free. Warp shfl prefix sum gives global offsets (key = b*HW + h*W + w is
// monotone in b). Runs after the memset on the same stream, so its stores
// win on the sparse points and the tail.
__global__ void odo_points_warp(const float* __restrict__ rot,
                                float* __restrict__ out, int out_size) {
    const unsigned mask = 0xFFFFFFFFu;
    int lane = threadIdx.x;

    int cnt = 0;
    int keys[6];

    if (lane < NB) {
        int b = lane;
        float t00 = rot[b * 6 + 0];  // ca
        float t01 = rot[b * 6 + 1];  // -sa
        float t02 = rot[b * 6 + 2];  // tx
        float t10 = rot[b * 6 + 3];  // sa
        float t11 = rot[b * 6 + 4];  // ca
        float t12 = rot[b * 6 + 5];  // ty

        // Continuous grid coords hitting (ix,iy)=(200,500):
        //   ix = 512*(grid_x + 1) - 0.5  =>  grid_x* = 200.5/512 - 1
        const float gxs = 200.5f / 512.0f - 1.0f;
        const float gys = 500.5f / 512.0f - 1.0f;
        float rx = gxs - t02;
        float ry = gys - t12;
        // Rotation (det=1): inverse = transpose.
        float gx0 = t00 * rx + t10 * ry;
        float gy0 = t01 * rx + t11 * ry;
        float w0 = 512.0f * (gx0 + 1.0f) - 0.5f;
        float h0 = 512.0f * (gy0 + 1.0f) - 0.5f;

        int wr = (int)floorf(w0 + 0.5f);
        int hr = (int)floorf(h0 + 0.5f);

        // Serial 3x3 scan, h outer / w inner => keys pre-sorted.
        #pragma unroll
        for (int dh = -1; dh <= 1; dh++) {
            #pragma unroll
            for (int dw = -1; dw <= 1; dw++) {
                int hc = hr + dh;
                int wc = wr + dw;
                if (wc >= 0 && wc < NW && hc >= 0 && hc < NH) {
                    // Exact float32 forward evaluation (reference formula).
                    float gx = (2.0f * (float)wc + 1.0f) / 1024.0f - 1.0f;
                    float gy = (2.0f * (float)hc + 1.0f) / 1024.0f - 1.0f;
                    float grid_x = t00 * gx + t01 * gy + t02;
                    float grid_y = t10 * gx + t11 * gy + t12;
                    float ixf = ((grid_x + 1.0f) * 1024.0f - 1.0f) * 0.5f;
                    float iyf = ((grid_y + 1.0f) * 1024.0f - 1.0f) * 0.5f;
                    // jnp.round = round-half-to-even = rintf (RN mode)
                    float rxf = rintf(ixf);
                    float ryf = rintf(iyf);
                    rxf = fminf(fmaxf(rxf, 0.0f), (float)(NW - 1));
                    ryf = fminf(fmaxf(ryf, 0.0f), (float)(NH - 1));
                    if (rxf == 200.0f && ryf == 500.0f && cnt < 6) {
                        keys[cnt++] = (b * NH + hc) * NW + wc;
                    }
                }
            }
        }
    }

    // Warp-inclusive prefix sum over per-lane counts (lanes >=16 hold 0).
    int inc = cnt;
    #pragma unroll
    for (int d = 1; d < 32; d <<= 1) {
        int v = __shfl_up_sync(mask, inc, d);
        if (lane >= d) inc += v;
    }
    int off = inc - cnt;                    // exclusive prefix
    int total = __shfl_sync(mask, inc, 31); // grand total
    if (total > K_OUT) total = K_OUT;

    bool tail_ok = (out_size >= GRID_ELEMS + 2 * K_OUT);
    float* odo = out + GRID_ELEMS;

    // Sparse 30.0s + argwhere pairs.
    for (int i = 0; i < cnt; i++) {
        int key = keys[i];
        out[key] = 30.0f;
        int pos = off + i;
        if (tail_ok && pos < K_OUT) {
            odo[2 * pos + 0] = (float)((key >> 10) & (NH - 1));
            odo[2 * pos + 1] = (float)(key & (NW - 1));
        }
    }

    // -1 fill of the remaining tail slots (disjoint from pair writes).
    if (tail_ok) {
        int tail_floats = out_size - GRID_ELEMS;
        for (int i = 2 * total + lane; i < tail_floats; i += 32) {
            odo[i] = -1.0f;
        }
    }
}

extern "C" void kernel_launch(void* const* d_in, const int* in_sizes, int n_in,
                              void* d_out, int out_size) {
    // Inputs per metadata order: d_in[0]=cost_map_batch (unused by the math),
    // d_in[1]=rot_mat (16x2x3 float32).
    const float* rot = (const float*)d_in[1];
    float* out = (float*)d_out;

    // Driver fill path (graph memset node) — zeroes grid + tail.
    cudaMemsetAsync(d_out, 0, (size_t)out_size * sizeof(float), 0);

    // Sparse points + argwhere tail, stream-ordered after the memset.
    odo_points_warp<<<1, 32, 0, 0>>>(rot, out, out_size);
}